// round 1
// baseline (speedup 1.0000x reference)
#include <cuda_runtime.h>
#include <math_constants.h>

// SplineNetwork: B=16384 queries in [-1,1]^2, 128x128 regular control grid,
// K=9 NN + Keys cubic-conv weighted sum. Inputs (metadata order):
//   d_in[0] = x              float32 (16384, 2)
//   d_in[1] = weights        float32 (16384, 1)
//   d_in[2] = control_points float32 (16384, 2)   cp[i*128+j] = (t_i, t_j)
// Output: tuple (out (16384,1), x (16384,2)) flattened -> 49152 floats.
//
// Selection must bit-match the reference's D = x2 + c2 - 2*(x@C^T) computed in
// fp32 with k-ascending FMA accumulation, and jax.lax.top_k's stable (lowest
// index first) tie-breaking. All candidates provably lie in a 5x5 index window
// around the nearest grid node.

#define NGRID 128
#define KNN   9
#define WIN   5

__global__ __launch_bounds__(128) void spline_knn_kernel(
    const float* __restrict__ x,
    const float* __restrict__ wts,
    const float* __restrict__ cp,
    float* __restrict__ out,
    int batch)
{
    __shared__ float t[NGRID];
    // t_i = cp[(i*NGRID + 0)*2 + 0]  (x-coord of row i, col 0)
    for (int i = threadIdx.x; i < NGRID; i += blockDim.x)
        t[i] = cp[i * NGRID * 2];
    __syncthreads();

    int b = blockIdx.x * blockDim.x + threadIdx.x;
    if (b >= batch) return;

    float x0 = x[2 * b];
    float x1 = x[2 * b + 1];

    // data-dependent bandwidth h = ||x[0] - x[1]||  (smooth; no bit-match needed)
    float hdx = __ldg(&x[0]) - __ldg(&x[2]);
    float hdy = __ldg(&x[1]) - __ldg(&x[3]);
    float hbw = sqrtf(__fadd_rn(__fmul_rn(hdx, hdx), __fmul_rn(hdy, hdy)));

    // x2 term exactly as reference: rn(rn(x0^2) + rn(x1^2))
    float x2s = __fadd_rn(__fmul_rn(x0, x0), __fmul_rn(x1, x1));

    // nearest grid index (window of +-2 absorbs any rounding slop)
    int nix = __float2int_rn((x0 + 1.0f) * 63.5f);
    int niy = __float2int_rn((x1 + 1.0f) * 63.5f);
    int sx = min(max(nix - 2, 0), NGRID - WIN);
    int sy = min(max(niy - 2, 0), NGRID - WIN);

    // top-9 by (D, idx) lexicographic, kept sorted ascending (all in registers)
    float bd[KNN];
    int   bi[KNN];
#pragma unroll
    for (int k = 0; k < KNN; ++k) { bd[k] = CUDART_INF_F; bi[k] = 0x7fffffff; }

#pragma unroll
    for (int dxi = 0; dxi < WIN; ++dxi) {
        int ix = sx + dxi;
        float cx  = t[ix];
        float cxx = __fmul_rn(cx, cx);
        float px  = __fmul_rn(x0, cx);          // rn(x0*cx)
#pragma unroll
        for (int dyi = 0; dyi < WIN; ++dyi) {
            int iy = sy + dyi;
            float cy  = t[iy];
            float c2  = __fadd_rn(cxx, __fmul_rn(cy, cy));      // rn(cx^2)+rn(cy^2)
            float dot = __fmaf_rn(x1, cy, px);                   // fma(x1,cy, rn(x0*cx))
            float D   = __fsub_rn(__fadd_rn(x2s, c2), __fmul_rn(2.0f, dot));
            int idx = (ix << 7) | iy;
            // strict < : equal-D newcomers (higher idx, since we iterate idx
            // ascending) are dropped/kept-after => matches top_k stability.
            if (D < bd[KNN - 1]) {
                bd[KNN - 1] = D;
                bi[KNN - 1] = idx;
#pragma unroll
                for (int k = KNN - 1; k > 0; --k) {
                    bool sw = bd[k] < bd[k - 1];
                    float td = sw ? bd[k] : bd[k - 1];
                    float tu = sw ? bd[k - 1] : bd[k];
                    int   ti = sw ? bi[k] : bi[k - 1];
                    int   tu2 = sw ? bi[k - 1] : bi[k];
                    bd[k - 1] = td; bd[k] = tu;
                    bi[k - 1] = ti; bi[k] = tu2;
                }
            }
        }
    }

    // epilogue: Keys cubic conv + weighted sum (smooth; plain fp32 fine)
    float acc = 0.0f;
#pragma unroll
    for (int k = 0; k < KNN; ++k) {
        int id = bi[k];
        float cx = t[id >> 7];
        float cy = t[id & (NGRID - 1)];
        float ddx = x0 - cx;
        float ddy = x1 - cy;
        float a = sqrtf(fmaf(ddx, ddx, ddy * ddy)) / hbw;   // a = |s|, s >= 0
        float cv;
        if (a < 1.0f)
            cv = fmaf(fmaf(1.5f, a, -2.5f), a * a, 1.0f);           // 1.5a^3-2.5a^2+1
        else if (a < 2.0f)
            cv = fmaf(fmaf(fmaf(-0.5f, a, 2.5f), a, -4.0f), a, 2.0f); // -0.5a^3+2.5a^2-4a+2
        else
            cv = 0.0f;
        acc = fmaf(__ldg(&wts[id]), cv, acc);
    }

    out[b] = acc;                 // out block  [0, B)
    out[batch + 2 * b]     = x0;  // x passthrough block [B, 3B)
    out[batch + 2 * b + 1] = x1;
}

extern "C" void kernel_launch(void* const* d_in, const int* in_sizes, int n_in,
                              void* d_out, int out_size)
{
    const float* x   = (const float*)d_in[0];
    const float* w   = (const float*)d_in[1];
    const float* cp  = (const float*)d_in[2];
    float* out = (float*)d_out;
    int batch = in_sizes[0] / 2;   // 16384
    int block = 128;
    int grid  = (batch + block - 1) / block;
    spline_knn_kernel<<<grid, block>>>(x, w, cp, out, batch);
    (void)n_in; (void)out_size;
}

// round 5
// speedup vs baseline: 1.0652x; 1.0652x over previous
#include <cuda_runtime.h>

// SplineNetwork: B=16384 queries in [-1,1]^2, 128x128 regular control grid,
// K=9 NN + Keys cubic-conv weighted sum.
//   d_in[0] = x (16384,2) f32 | d_in[1] = weights (16384,1) f32
//   d_in[2] = control_points (16384,2) f32, cp[i*128+j] = (t_i, t_j)
// Output: (out (16384,1), x (16384,2)) -> 49152 floats.
//
// Window: ROUND-based 5x5 {nix-2..nix+2}, clamped to [0,123]. Certified by R1
// (rel_err 7.8e-8). Floor-based windows FAIL at domain-edge columns where the
// 9th-NN radius^2 grows to ~4.5h^2 (R2/R3 bug): round coverage >=1.5h/side,
// out-of-window D >= 6.25h^2 > worst-case 9th 4.5h^2 incl. clamped corners.
// D bit-matches reference: rn(rn(x2s + c2) - 2*fma(x1,cy,rn(x0*cx)));
// ties -> ascending global index == enumeration order (top_k stability).

#define NGRID 128
#define WIN   5
#define NC    (WIN * WIN)

__global__ __launch_bounds__(64) void spline_knn_kernel(
    const float* __restrict__ x,
    const float* __restrict__ wts,
    const float* __restrict__ cp,
    float* __restrict__ out,
    int batch)
{
    __shared__ float t[NGRID];
    for (int i = threadIdx.x; i < NGRID; i += blockDim.x)
        t[i] = cp[2 * i + 1];          // t_j = y-coord of node (0,j) = linspace[j]
    __syncthreads();

    int b = blockIdx.x * blockDim.x + threadIdx.x;
    if (b >= batch) return;

    float2 xv = __ldg((const float2*)x + b);
    float x0 = xv.x, x1 = xv.y;

    // bandwidth h = ||x[0]-x[1]|| (smooth; no bit-match needed)
    float4 h4 = __ldg((const float4*)x);
    float hdx = h4.x - h4.z;
    float hdy = h4.y - h4.w;
    float inv_h = 1.0f / sqrtf(__fadd_rn(__fmul_rn(hdx, hdx), __fmul_rn(hdy, hdy)));

    // ROUND-based window center (R1-certified), clamped
    int nix = __float2int_rn((x0 + 1.0f) * 63.5f);
    int niy = __float2int_rn((x1 + 1.0f) * 63.5f);
    int sx = min(max(nix - 2, 0), NGRID - WIN);
    int sy = min(max(niy - 2, 0), NGRID - WIN);

    // speculative prefetch of all 25 window weights (overlaps selection math)
    float w[NC];
#pragma unroll
    for (int r = 0; r < WIN; ++r) {
        int base = ((sx + r) << 7) + sy;
#pragma unroll
        for (int c = 0; c < WIN; ++c)
            w[r * WIN + c] = __ldg(&wts[base + c]);
    }

    float tx[WIN], ty[WIN];
#pragma unroll
    for (int r = 0; r < WIN; ++r) { tx[r] = t[sx + r]; ty[r] = t[sy + r]; }

    // exact reference arithmetic for D
    float x2s = __fadd_rn(__fmul_rn(x0, x0), __fmul_rn(x1, x1));
    float cxx[WIN], px[WIN], cyy[WIN];
#pragma unroll
    for (int r = 0; r < WIN; ++r) {
        cxx[r] = __fmul_rn(tx[r], tx[r]);
        px[r]  = __fmul_rn(x0, tx[r]);
        cyy[r] = __fmul_rn(ty[r], ty[r]);
    }

    float D[NC];
#pragma unroll
    for (int r = 0; r < WIN; ++r) {
#pragma unroll
        for (int c = 0; c < WIN; ++c) {
            float c2  = __fadd_rn(cxx[r], cyy[c]);
            float dot = __fmaf_rn(x1, ty[c], px[r]);
            D[r * WIN + c] = __fsub_rn(__fadd_rn(x2s, c2), __fmul_rn(2.0f, dot));
        }
    }

    // branch-free stable rank: enumeration order == ascending global index,
    // ties -> lower index wins (top_k stability). rank is a permutation of
    // 0..24; node selected iff rank < 9.
    int rank[NC];
#pragma unroll
    for (int i = 0; i < NC; ++i) rank[i] = 0;
#pragma unroll
    for (int i = 0; i < NC; ++i) {
#pragma unroll
        for (int j = i + 1; j < NC; ++j) {
            bool jlt = D[j] < D[i];
            rank[i] += jlt ? 1 : 0;
            rank[j] += jlt ? 0 : 1;
        }
    }

    // epilogue: Keys cubic conv, predicated accumulate over the 9 selected
    float dx2[WIN], dyv[WIN];
#pragma unroll
    for (int r = 0; r < WIN; ++r) {
        float dxv = x0 - tx[r];
        dx2[r] = dxv * dxv;
        dyv[r] = x1 - ty[r];
    }

    float acc = 0.0f;
#pragma unroll
    for (int r = 0; r < WIN; ++r) {
#pragma unroll
        for (int c = 0; c < WIN; ++c) {
            int i = r * WIN + c;
            float a = sqrtf(fmaf(dyv[c], dyv[c], dx2[r])) * inv_h;
            float p1 = fmaf(fmaf(1.5f, a, -2.5f), a * a, 1.0f);
            float p2 = fmaf(fmaf(fmaf(-0.5f, a, 2.5f), a, -4.0f), a, 2.0f);
            float cv = (a < 1.0f) ? p1 : ((a < 2.0f) ? p2 : 0.0f);
            cv = (rank[i] < 9) ? cv : 0.0f;
            acc = fmaf(w[i], cv, acc);
        }
    }

    out[b] = acc;
    ((float2*)(out + batch))[b] = xv;   // x passthrough
}

extern "C" void kernel_launch(void* const* d_in, const int* in_sizes, int n_in,
                              void* d_out, int out_size)
{
    const float* x  = (const float*)d_in[0];
    const float* w  = (const float*)d_in[1];
    const float* cp = (const float*)d_in[2];
    float* out = (float*)d_out;
    int batch = in_sizes[0] / 2;   // 16384
    int block = 64;
    int grid  = (batch + block - 1) / block;
    spline_knn_kernel<<<grid, block>>>(x, w, cp, out, batch);
    (void)n_in; (void)out_size;
}